// round 1
// baseline (speedup 1.0000x reference)
#include <cuda_runtime.h>
#include <math.h>

#define Bsz 2
#define Sseq 2048
#define Dmodel 2048
#define Hheads 16
#define HDdim 128

// scratch (no cudaMalloc allowed)
__device__ float g_Q[Bsz * Sseq * Dmodel];
__device__ float g_K[Bsz * Sseq * Dmodel];
__device__ float g_V[Bsz * Sseq * Dmodel];
__device__ float g_Y[Bsz * Sseq * Dmodel];

// ---------------------------------------------------------------------------
// GEMM: C[M,N] = A[M,K] * B[N,K]^T   (both operands K-contiguous, like x @ W.T)
// 128x128 block, 256 threads, 8x8 per thread, BK=8, register prefetch.
// ---------------------------------------------------------------------------
#define GBM 128
#define GBN 128
#define GBK 8

__global__ __launch_bounds__(256) void gemm_nt(const float* __restrict__ A,
                                               const float* __restrict__ B,
                                               float* __restrict__ C,
                                               int M, int N, int K)
{
    __shared__ float As[GBK][GBM + 4];
    __shared__ float Bs[GBK][GBN + 4];

    const int tid = threadIdx.x;
    const int tx = tid & 15;        // 0..15 -> col group
    const int ty = tid >> 4;        // 0..15 -> row group
    const int rowBase = blockIdx.y * GBM;
    const int colBase = blockIdx.x * GBN;

    // load mapping: each thread loads one float4 of A and one of B per k-tile
    const int lr = tid >> 1;              // 0..127
    const int lc = (tid & 1) * 4;         // 0 or 4

    const float* Aptr = A + (size_t)(rowBase + lr) * K + lc;
    const float* Bptr = B + (size_t)(colBase + lr) * K + lc;

    float4 a4 = *(const float4*)Aptr;
    float4 b4 = *(const float4*)Bptr;

    float acc[8][8];
#pragma unroll
    for (int i = 0; i < 8; i++)
#pragma unroll
        for (int j = 0; j < 8; j++) acc[i][j] = 0.f;

    const int nt = K / GBK;
    for (int kt = 0; kt < nt; kt++) {
        As[lc + 0][lr] = a4.x; As[lc + 1][lr] = a4.y;
        As[lc + 2][lr] = a4.z; As[lc + 3][lr] = a4.w;
        Bs[lc + 0][lr] = b4.x; Bs[lc + 1][lr] = b4.y;
        Bs[lc + 2][lr] = b4.z; Bs[lc + 3][lr] = b4.w;
        __syncthreads();

        if (kt + 1 < nt) {
            a4 = *(const float4*)(Aptr + (size_t)(kt + 1) * GBK);
            b4 = *(const float4*)(Bptr + (size_t)(kt + 1) * GBK);
        }

#pragma unroll
        for (int kk = 0; kk < GBK; kk++) {
            float ra[8], rb[8];
            *(float4*)&ra[0] = *(const float4*)&As[kk][ty * 8];
            *(float4*)&ra[4] = *(const float4*)&As[kk][ty * 8 + 4];
            *(float4*)&rb[0] = *(const float4*)&Bs[kk][tx * 8];
            *(float4*)&rb[4] = *(const float4*)&Bs[kk][tx * 8 + 4];
#pragma unroll
            for (int i = 0; i < 8; i++)
#pragma unroll
                for (int j = 0; j < 8; j++)
                    acc[i][j] += ra[i] * rb[j];
        }
        __syncthreads();
    }

#pragma unroll
    for (int i = 0; i < 8; i++) {
        const int r = rowBase + ty * 8 + i;
        float4* crow = (float4*)&C[(size_t)r * N + colBase + tx * 8];
        crow[0] = make_float4(acc[i][0], acc[i][1], acc[i][2], acc[i][3]);
        crow[1] = make_float4(acc[i][4], acc[i][5], acc[i][6], acc[i][7]);
    }
}

// ---------------------------------------------------------------------------
// Flash-style causal attention. One CTA = (b, h, 64-query tile).
// Q/K/V layout: (b, s, D) with head slice at column h*128.
// Output Y written in (b, s, D) layout (heads concatenated) ready for Wo GEMM.
// ---------------------------------------------------------------------------
#define ABM 64
#define ABN 64
#define QPAD (HDdim + 1)
#define PPAD (ABN + 1)

// smem floats: 3*64*129 (Q,K,V) + 64*65 (P) + 3*64 (m,l,alpha)
#define ATTN_SMEM_FLOATS (3 * 64 * QPAD + 64 * PPAD + 192)
#define ATTN_SMEM_BYTES (ATTN_SMEM_FLOATS * 4)

__global__ __launch_bounds__(256) void attn_kernel(const float* __restrict__ Q,
                                                   const float* __restrict__ K,
                                                   const float* __restrict__ V,
                                                   float* __restrict__ Y)
{
    extern __shared__ float sm[];
    float (*Qs)[QPAD] = (float(*)[QPAD])sm;
    float (*Ks)[QPAD] = (float(*)[QPAD])(sm + 64 * QPAD);
    float (*Vs)[QPAD] = (float(*)[QPAD])(sm + 2 * 64 * QPAD);
    float (*Ps)[PPAD] = (float(*)[PPAD])(sm + 3 * 64 * QPAD);
    float* m_sh = sm + 3 * 64 * QPAD + 64 * PPAD;
    float* l_sh = m_sh + 64;
    float* al_sh = l_sh + 64;

    const int tid = threadIdx.x;
    const int tx = tid & 15;
    const int ty = tid >> 4;
    const int qt = blockIdx.x;
    const int h = blockIdx.y;
    const int b = blockIdx.z;

    const float scale = 0.08838834764831845f;  // 1/sqrt(128)

    const size_t base = ((size_t)b * Sseq) * Dmodel + (size_t)h * HDdim;

    // load Q tile (64 x 128)
#pragma unroll
    for (int it = 0; it < 8; it++) {
        int idx = it * 256 + tid;     // float4 index, 2048 total
        int r = idx >> 5;             // 32 float4 per row
        int c = (idx & 31) << 2;
        float4 v = *(const float4*)&Q[base + (size_t)(qt * ABM + r) * Dmodel + c];
        Qs[r][c] = v.x; Qs[r][c + 1] = v.y; Qs[r][c + 2] = v.z; Qs[r][c + 3] = v.w;
    }
    if (tid < 64) { m_sh[tid] = -INFINITY; l_sh[tid] = 0.f; }

    float O[4][8];
#pragma unroll
    for (int i = 0; i < 4; i++)
#pragma unroll
        for (int j = 0; j < 8; j++) O[i][j] = 0.f;

    for (int kt = 0; kt <= qt; kt++) {
        __syncthreads();   // protect Ks/Vs from previous iteration's readers
        // load K, V tiles
#pragma unroll
        for (int it = 0; it < 8; it++) {
            int idx = it * 256 + tid;
            int r = idx >> 5;
            int c = (idx & 31) << 2;
            float4 kv = *(const float4*)&K[base + (size_t)(kt * ABN + r) * Dmodel + c];
            Ks[r][c] = kv.x; Ks[r][c + 1] = kv.y; Ks[r][c + 2] = kv.z; Ks[r][c + 3] = kv.w;
            float4 vv = *(const float4*)&V[base + (size_t)(kt * ABN + r) * Dmodel + c];
            Vs[r][c] = vv.x; Vs[r][c + 1] = vv.y; Vs[r][c + 2] = vv.z; Vs[r][c + 3] = vv.w;
        }
        __syncthreads();

        // Phase A: S = Q K^T (rows 4ty+i, cols 4tx+j)
        float s[4][4];
#pragma unroll
        for (int i = 0; i < 4; i++)
#pragma unroll
            for (int j = 0; j < 4; j++) s[i][j] = 0.f;

#pragma unroll 8
        for (int kk = 0; kk < HDdim; kk++) {
            float qa[4], kb[4];
#pragma unroll
            for (int i = 0; i < 4; i++) qa[i] = Qs[4 * ty + i][kk];
#pragma unroll
            for (int j = 0; j < 4; j++) kb[j] = Ks[4 * tx + j][kk];
#pragma unroll
            for (int i = 0; i < 4; i++)
#pragma unroll
                for (int j = 0; j < 4; j++)
                    s[i][j] += qa[i] * kb[j];
        }
        const int q0 = qt * ABM + 4 * ty;
        const int k0 = kt * ABN + 4 * tx;
#pragma unroll
        for (int i = 0; i < 4; i++)
#pragma unroll
            for (int j = 0; j < 4; j++) {
                float val = (k0 + j > q0 + i) ? -INFINITY : s[i][j] * scale;
                Ps[4 * ty + i][4 * tx + j] = val;
            }
        __syncthreads();

        // Phase B: per-row online softmax update (64 rows, 1 thread each)
        if (tid < 64) {
            float mold = m_sh[tid];
            float mx = mold;
            for (int j = 0; j < ABN; j++) mx = fmaxf(mx, Ps[tid][j]);
            float a = (mold == -INFINITY) ? 0.f : __expf(mold - mx);
            float ls = 0.f;
            for (int j = 0; j < ABN; j++) {
                float pv = Ps[tid][j];
                float e = (pv == -INFINITY) ? 0.f : __expf(pv - mx);
                Ps[tid][j] = e;
                ls += e;
            }
            m_sh[tid] = mx;
            l_sh[tid] = l_sh[tid] * a + ls;
            al_sh[tid] = a;
        }
        __syncthreads();

        // Phase C: rescale O, accumulate P @ V (rows 4ty+i, cols tx + 16j)
        float ar[4];
#pragma unroll
        for (int i = 0; i < 4; i++) ar[i] = al_sh[4 * ty + i];
#pragma unroll
        for (int i = 0; i < 4; i++)
#pragma unroll
            for (int j = 0; j < 8; j++) O[i][j] *= ar[i];

#pragma unroll 4
        for (int kk = 0; kk < ABN; kk++) {
            float p[4], vv[8];
#pragma unroll
            for (int i = 0; i < 4; i++) p[i] = Ps[4 * ty + i][kk];
#pragma unroll
            for (int j = 0; j < 8; j++) vv[j] = Vs[kk][tx + 16 * j];
#pragma unroll
            for (int i = 0; i < 4; i++)
#pragma unroll
                for (int j = 0; j < 8; j++)
                    O[i][j] += p[i] * vv[j];
        }
    }

    float linv[4];
#pragma unroll
    for (int i = 0; i < 4; i++) linv[i] = 1.f / l_sh[4 * ty + i];
#pragma unroll
    for (int i = 0; i < 4; i++) {
        size_t row = base + (size_t)(qt * ABM + 4 * ty + i) * Dmodel;
#pragma unroll
        for (int j = 0; j < 8; j++)
            Y[row + tx + 16 * j] = O[i][j] * linv[i];
    }
}

// ---------------------------------------------------------------------------
// launch
// ---------------------------------------------------------------------------
extern "C" void kernel_launch(void* const* d_in, const int* in_sizes, int n_in,
                              void* d_out, int out_size)
{
    (void)in_sizes; (void)n_in; (void)out_size;
    const float* x  = (const float*)d_in[0];
    // d_in[1] = mask (structurally causal triu(k=1); implemented analytically)
    const float* Wq = (const float*)d_in[2];
    const float* Wk = (const float*)d_in[3];
    const float* Wv = (const float*)d_in[4];
    const float* Wo = (const float*)d_in[5];
    float* out = (float*)d_out;

    float *qp, *kp, *vp, *yp;
    cudaGetSymbolAddress((void**)&qp, g_Q);
    cudaGetSymbolAddress((void**)&kp, g_K);
    cudaGetSymbolAddress((void**)&vp, g_V);
    cudaGetSymbolAddress((void**)&yp, g_Y);

    const int M = Bsz * Sseq;           // 4096
    dim3 ggrid(Dmodel / GBN, M / GBM);  // (16, 32)

    gemm_nt<<<ggrid, 256>>>(x, Wq, qp, M, Dmodel, Dmodel);
    gemm_nt<<<ggrid, 256>>>(x, Wk, kp, M, Dmodel, Dmodel);
    gemm_nt<<<ggrid, 256>>>(x, Wv, vp, M, Dmodel, Dmodel);

    cudaFuncSetAttribute(attn_kernel, cudaFuncAttributeMaxDynamicSharedMemorySize,
                         ATTN_SMEM_BYTES);
    attn_kernel<<<dim3(Sseq / ABM, Hheads, Bsz), 256, ATTN_SMEM_BYTES>>>(qp, kp, vp, yp);

    gemm_nt<<<ggrid, 256>>>(yp, Wo, out, M, Dmodel, Dmodel);
}